// round 6
// baseline (speedup 1.0000x reference)
#include <cuda_runtime.h>
#include <cstdint>

// Problem constants (fixed by the reference: B=16, L=4096, D=512, WORD_SIZE=128, WORD_LEN=2)
#define NWORDS 32768     // B * (L/2)
#define DIM    512
#define NC     128       // codebook rows
#define BM     128       // words per CTA tile
#define BK     16        // k-chunk
#define BMP    (BM + 4)  // padded smem leading dim
#define NCP    (NC + 4)

// Scratch (no allocations allowed -> __device__ globals)
__device__ float g_s_tab[NC];      // ||P_c - C_c||^2 per code
__device__ float g_cnorm[NC];      // ||C_c||^2 per code
__device__ int   g_count[NC];      // histogram of argmin indices
__device__ float g_mnorm[NWORDS];  // ||m_w||^2 per word, XLA/LLVM-order bitwise

// ---------------------------------------------------------------------------
// Kernel 0: per-code prep: cnorm[c], s[c] = ||C@W^T + b - C||^2 row c ; zero counts.
// (Only feeds the loss scalar and the d2 "+cnorm" term; cnorm order noise ~1e-9
//  is far below the 3e-5 decision granularity, so plain fp32 order is fine.)
// ---------------------------------------------------------------------------
__global__ void prep_kernel(const float* __restrict__ cb,
                            const float* __restrict__ W,
                            const float* __restrict__ bias) {
    const int c = blockIdx.x;
    const int t = threadIdx.x;          // 256 threads
    __shared__ float csm[DIM];
    __shared__ float warp_s[8];
    __shared__ float warp_n[8];

    if (t == 0) g_count[c] = 0;

    float nacc = 0.f;
    for (int i = t; i < DIM; i += 256) {
        float v = cb[(size_t)c * DIM + i];
        csm[i] = v;
        nacc += v * v;
    }
    __syncthreads();

    const int wp = t >> 5, ln = t & 31;

    #pragma unroll
    for (int o = 16; o; o >>= 1) nacc += __shfl_down_sync(0xffffffffu, nacc, o);
    if (ln == 0) warp_n[wp] = nacc;

    float sacc = 0.f;
    for (int d = wp; d < DIM; d += 8) {
        const float* wr = W + (size_t)d * DIM;
        float p = 0.f;
        #pragma unroll 4
        for (int k = ln; k < DIM; k += 32) p += csm[k] * wr[k];
        #pragma unroll
        for (int o = 16; o; o >>= 1) p += __shfl_down_sync(0xffffffffu, p, o);
        if (ln == 0) {
            float diff = p + bias[d] - csm[d];
            sacc += diff * diff;
        }
    }
    if (ln == 0) warp_s[wp] = sacc;
    __syncthreads();

    if (t == 0) {
        float s = 0.f, n = 0.f;
        #pragma unroll
        for (int i = 0; i < 8; i++) { s += warp_s[i]; n += warp_n[i]; }
        g_s_tab[c] = s;
        g_cnorm[c] = n;
    }
}

// ---------------------------------------------------------------------------
// Kernel 0b: mnorm[w] = sum_k m_k^2 replicating XLA-CPU (LLVM aarch64) reduce:
//   VF=4 (NEON), IC=4  ->  16 strided accumulators:
//       part_p[l] = sum_{i=0..31} y[16 i + 4 p + l]   (sequential over i)
//   part combine (left fold):  v = ((P0 + P1) + P2) + P3   (lanewise)
//   lane combine (faddp tree): mnorm = (v0 + v1) + (v2 + v3)
//   with y[k] = fl(m_k^2), m_k = fl(fl(a_k + b_k) * 0.5).
// One 16-lane half-warp per word; lane (4p+l) owns one sequential chain.
// All ops __fadd_rn/__fmul_rn (no contraction/reassociation).
// ---------------------------------------------------------------------------
__global__ void mnorm_kernel(const float* __restrict__ emb) {
    const int gt   = blockIdx.x * blockDim.x + threadIdx.x;
    const int word = gt >> 4;
    const int l16  = threadIdx.x & 15;
    if (word >= NWORDS) return;

    const float* A = emb + (size_t)word * 2 * DIM;
    const float* B = A + DIM;

    float acc = 0.f;
    #pragma unroll 8
    for (int i = 0; i < 32; i++) {
        const int k = 16 * i + l16;
        float m = __fmul_rn(__fadd_rn(__ldg(&A[k]), __ldg(&B[k])), 0.5f);
        acc = __fadd_rn(acc, __fmul_rn(m, m));
    }

    // part fold: every lane gathers the four parts for its l = l16 & 3
    const unsigned FULL = 0xffffffffu;
    const int l = l16 & 3;
    float P0 = __shfl_sync(FULL, acc, l + 0, 16);
    float P1 = __shfl_sync(FULL, acc, l + 4, 16);
    float P2 = __shfl_sync(FULL, acc, l + 8, 16);
    float P3 = __shfl_sync(FULL, acc, l + 12, 16);
    float r = __fadd_rn(__fadd_rn(__fadd_rn(P0, P1), P2), P3);  // r[l]

    // lane tree (faddp): (r0 + r1) + (r2 + r3)
    float r0 = __shfl_sync(FULL, r, 0, 16);
    float r1 = __shfl_sync(FULL, r, 1, 16);
    float r2 = __shfl_sync(FULL, r, 2, 16);
    float r3 = __shfl_sync(FULL, r, 3, 16);
    if (l16 == 0)
        g_mnorm[word] = __fadd_rn(__fadd_rn(r0, r1), __fadd_rn(r2, r3));
}

// ---------------------------------------------------------------------------
// Kernel 1: fused pair-sum -> fp32 score GEMM -> reference rounding chain ->
//           argmin -> index write -> histogram -> codebook gather-write.
//
// smem A holds fl(a+b) = 2 * word_mean exactly; the per-thread accumulator is
// a single sequential fma chain over ascending k — the same chain Eigen's
// gebp uses for ein — so acc == 2*ein BITWISE (power-of-2 scaling commutes
// with every fp32 rounding). Final: d2 = fl(fl(mnorm - acc) + cnorm), the
// reference's exact expression (mnorm - 2*ein) + cnorm.
// ---------------------------------------------------------------------------
__global__ __launch_bounds__(256, 2)
void main_kernel(const float* __restrict__ emb,   // [NWORDS*2, DIM]
                 const float* __restrict__ cb,    // [NC, DIM]
                 float* __restrict__ out_idx,     // NWORDS floats
                 float* __restrict__ out_emb) {   // NWORDS*DIM floats
    __shared__ float sm_m[BK][BMP];
    __shared__ float sm_c[BK][NCP];
    __shared__ int   widx[BM];
    __shared__ int   hist[NC];

    const int t = threadIdx.x;
    const int wbase = blockIdx.x * BM;

    if (t < NC) hist[t] = 0;

    const int wo = t >> 4;   // 0..15: word group (8 words each)
    const int co = t & 15;   // 0..15: code group (8 codes each)

    float acc[8][8];
    #pragma unroll
    for (int i = 0; i < 8; i++)
        #pragma unroll
        for (int j = 0; j < 8; j++) acc[i][j] = 0.f;

    const int lw = t >> 2;   // 0..63
    const int lq = t & 3;    // 0..3

    for (int kc = 0; kc < DIM; kc += BK) {
        __syncthreads();
        // A tile: fl(a+b) -> transposed smem
        #pragma unroll
        for (int p = 0; p < 2; p++) {
            const int wt = p * 64 + lw;
            const size_t row = (size_t)(wbase + wt) * 2 * DIM + kc + lq * 4;
            float4 r0 = *(const float4*)(emb + row);
            float4 r1 = *(const float4*)(emb + row + DIM);
            sm_m[lq * 4 + 0][wt] = __fadd_rn(r0.x, r1.x);
            sm_m[lq * 4 + 1][wt] = __fadd_rn(r0.y, r1.y);
            sm_m[lq * 4 + 2][wt] = __fadd_rn(r0.z, r1.z);
            sm_m[lq * 4 + 3][wt] = __fadd_rn(r0.w, r1.w);
        }
        // B tile: codebook chunk -> transposed smem
        #pragma unroll
        for (int p = 0; p < 2; p++) {
            const int ct = p * 64 + lw;
            float4 r = *(const float4*)(cb + (size_t)ct * DIM + kc + lq * 4);
            sm_c[lq * 4 + 0][ct] = r.x;
            sm_c[lq * 4 + 1][ct] = r.y;
            sm_c[lq * 4 + 2][ct] = r.z;
            sm_c[lq * 4 + 3][ct] = r.w;
        }
        __syncthreads();

        #pragma unroll
        for (int k = 0; k < BK; k++) {
            float a[8], b[8];
            *(float4*)(a)     = *(const float4*)&sm_m[k][wo * 8];
            *(float4*)(a + 4) = *(const float4*)&sm_m[k][wo * 8 + 4];
            *(float4*)(b)     = *(const float4*)&sm_c[k][co * 8];
            *(float4*)(b + 4) = *(const float4*)&sm_c[k][co * 8 + 4];
            #pragma unroll
            for (int i = 0; i < 8; i++)
                #pragma unroll
                for (int j = 0; j < 8; j++)
                    acc[i][j] = __fmaf_rn(a[i], b[j], acc[i][j]); // sequential k-chain
        }
    }

    // Reference epilogue pieces
    float cn[8];
    #pragma unroll
    for (int j = 0; j < 8; j++) cn[j] = __ldg(&g_cnorm[co * 8 + j]);
    float mn[8];
    #pragma unroll
    for (int i = 0; i < 8; i++) mn[i] = __ldg(&g_mnorm[wbase + wo * 8 + i]);

    // Argmin on d2 = fl(fl(mnorm - acc) + cnorm); first-min tie-break.
    #pragma unroll
    for (int i = 0; i < 8; i++) {
        float best;
        int bidx = co * 8;
        {
            float tt = __fadd_rn(mn[i], -acc[i][0]);
            best = __fadd_rn(tt, cn[0]);
        }
        #pragma unroll
        for (int j = 1; j < 8; j++) {
            float tt = __fadd_rn(mn[i], -acc[i][j]);
            float d2 = __fadd_rn(tt, cn[j]);
            if (d2 < best) { best = d2; bidx = co * 8 + j; }
        }
        #pragma unroll
        for (int o = 8; o; o >>= 1) {
            float s2 = __shfl_down_sync(0xffffffffu, best, o, 16);
            int   i2 = __shfl_down_sync(0xffffffffu, bidx, o, 16);
            if (s2 < best || (s2 == best && i2 < bidx)) { best = s2; bidx = i2; }
        }
        if (co == 0) {
            const int w = wo * 8 + i;
            widx[w] = bidx;
            out_idx[wbase + w] = (float)bidx;
            atomicAdd(&hist[bidx], 1);
        }
    }
    __syncthreads();

    if (t < NC) {
        int h = hist[t];
        if (h) atomicAdd(&g_count[t], h);
    }

    // Gather-write word_embeddings (codebook rows L2-hot, coalesced stores)
    for (int f = t; f < BM * (DIM / 4); f += 256) {
        const int w  = f >> 7;
        const int c4 = f & 127;
        const int c  = widx[w];
        float4 v = *(const float4*)(cb + (size_t)c * DIM + c4 * 4);
        *(float4*)(out_emb + (size_t)(wbase + w) * DIM + c4 * 4) = v;
    }
}

// ---------------------------------------------------------------------------
// Kernel 2: loss = sum_c count[c]*s[c] / (NWORDS*DIM)
// ---------------------------------------------------------------------------
__global__ void loss_kernel(float* __restrict__ out_loss) {
    const int t = threadIdx.x;  // 128 threads
    __shared__ float ws[4];
    float v = (float)g_count[t] * g_s_tab[t];
    #pragma unroll
    for (int o = 16; o; o >>= 1) v += __shfl_down_sync(0xffffffffu, v, o);
    if ((t & 31) == 0) ws[t >> 5] = v;
    __syncthreads();
    if (t == 0) {
        float s = ws[0] + ws[1] + ws[2] + ws[3];
        out_loss[0] = s * (1.0f / ((float)NWORDS * (float)DIM));
    }
}

// ---------------------------------------------------------------------------
// Inputs (metadata order):
//   d_in[0] char_tokens int32 (unused)  d_in[1] char_embeddings f32 [16,4096,512]
//   d_in[2] word_codebook f32 [128,512] d_in[3] proj_w f32 [512,512]
//   d_in[4] proj_b f32 [512]
// Output (f32, flattened): [0,32768) indices | [.., +32768*512) embeddings | [last] loss
// ---------------------------------------------------------------------------
extern "C" void kernel_launch(void* const* d_in, const int* in_sizes, int n_in,
                              void* d_out, int out_size) {
    const float* emb = (const float*)d_in[1];
    const float* cb  = (const float*)d_in[2];
    const float* W   = (const float*)d_in[3];
    const float* b   = (const float*)d_in[4];
    float* out = (float*)d_out;

    float* out_idx  = out;
    float* out_emb  = out + NWORDS;
    float* out_loss = out + NWORDS + (size_t)NWORDS * DIM;

    prep_kernel<<<NC, 256>>>(cb, W, b);
    mnorm_kernel<<<(NWORDS * 16) / 256, 256>>>(emb);
    main_kernel<<<NWORDS / BM, 256>>>(emb, cb, out_idx, out_emb);
    loss_kernel<<<1, NC>>>(out_loss);
}

// round 7
// speedup vs baseline: 1.0875x; 1.0875x over previous
#include <cuda_runtime.h>
#include <cstdint>

// Problem constants (fixed by the reference: B=16, L=4096, D=512, WORD_SIZE=128, WORD_LEN=2)
#define NWORDS 32768     // B * (L/2)
#define DIM    512
#define NC     128       // codebook rows
#define BM     128       // words per CTA tile
#define BK     16        // k-chunk
#define BMP    (BM + 4)  // padded smem leading dim
#define NCP    (NC + 4)
#define NCHUNK (DIM / BK)

// Scratch (no allocations allowed -> __device__ globals)
__device__ float    g_s_tab[NC];   // ||P_c - C_c||^2 per code
__device__ float    g_cnorm[NC];   // ||C_c||^2 per code
__device__ int      g_count[NC];   // histogram of argmin indices
__device__ unsigned g_done;        // last-CTA election (zero-init; reset by last CTA)

// ---- packed f32x2 helpers (each half = independent IEEE fp32 op) -----------
__device__ __forceinline__ unsigned long long dup2(float x) {
    unsigned long long r;
    asm("mov.b64 %0, {%1, %1};" : "=l"(r) : "f"(x));
    return r;
}
__device__ __forceinline__ void ffma2(unsigned long long& d,
                                      unsigned long long a,
                                      unsigned long long b) {
    asm("fma.rn.f32x2 %0, %1, %2, %0;" : "+l"(d) : "l"(a), "l"(b));
}
__device__ __forceinline__ float2 unpack2(unsigned long long v) {
    float2 f;
    asm("mov.b64 {%0, %1}, %2;" : "=f"(f.x), "=f"(f.y) : "l"(v));
    return f;
}

// ---------------------------------------------------------------------------
// Kernel 0: per-code prep: cnorm[c], s[c] = ||C@W^T + b - C||^2 ; zero counts.
// (Feeds only the loss scalar and the d2 "+cnorm" term; fp32 order noise
//  ~1e-9 is far below the 3e-5 decision granularity.)
// ---------------------------------------------------------------------------
__global__ void prep_kernel(const float* __restrict__ cb,
                            const float* __restrict__ W,
                            const float* __restrict__ bias) {
    const int c = blockIdx.x;
    const int t = threadIdx.x;          // 256 threads
    __shared__ float csm[DIM];
    __shared__ float warp_s[8];
    __shared__ float warp_n[8];

    if (t == 0) g_count[c] = 0;

    float nacc = 0.f;
    for (int i = t; i < DIM; i += 256) {
        float v = cb[(size_t)c * DIM + i];
        csm[i] = v;
        nacc += v * v;
    }
    __syncthreads();

    const int wp = t >> 5, ln = t & 31;

    #pragma unroll
    for (int o = 16; o; o >>= 1) nacc += __shfl_down_sync(0xffffffffu, nacc, o);
    if (ln == 0) warp_n[wp] = nacc;

    float sacc = 0.f;
    for (int d = wp; d < DIM; d += 8) {
        const float* wr = W + (size_t)d * DIM;
        float p = 0.f;
        #pragma unroll 4
        for (int k = ln; k < DIM; k += 32) p += csm[k] * wr[k];
        #pragma unroll
        for (int o = 16; o; o >>= 1) p += __shfl_down_sync(0xffffffffu, p, o);
        if (ln == 0) {
            float diff = p + bias[d] - csm[d];
            sacc += diff * diff;
        }
    }
    if (ln == 0) warp_s[wp] = sacc;
    __syncthreads();

    if (t == 0) {
        float s = 0.f, n = 0.f;
        #pragma unroll
        for (int i = 0; i < 8; i++) { s += warp_s[i]; n += warp_n[i]; }
        g_s_tab[c] = s;
        g_cnorm[c] = n;
    }
}

// ---------------------------------------------------------------------------
// Kernel 1: fused  pair-sum -> mnorm(LLVM-order) -> fp32 GEMM (f32x2 packed)
//           -> reference rounding chain -> argmin -> histogram -> gather
//           -> last-CTA loss.
//
// Bit-exactness invariants (all verified PASS in round 6, preserved here):
//  * per-(word,code) dot: single fp32 accumulator, FMA over ascending k.
//    f32x2 halves are independent fp32 FMAs -> chains unchanged.
//  * mnorm: 16 chains part_p[l] = sum_i y[16i+4p+l] (i = kc/16 ascending;
//    loader thread lq == p, component == l), fold ((P0+P1)+P2)+P3 then
//    (v0+v1)+(v2+v3), y = fl(m^2), m = fl(fl(a+b)*0.5).
//  * d2 = fl(fl(mnorm - acc) + cnorm), first-min tie-break.
// ---------------------------------------------------------------------------
__global__ __launch_bounds__(256, 2)
void main_kernel(const float* __restrict__ emb,   // [NWORDS*2, DIM]
                 const float* __restrict__ cb,    // [NC, DIM]
                 float* __restrict__ out_idx,     // NWORDS floats
                 float* __restrict__ out_emb,     // NWORDS*DIM floats
                 float* __restrict__ out_loss) {  // 1 float
    __shared__ float sm_m[BK][BMP];
    __shared__ float sm_c[BK][NCP];
    __shared__ float sm_fold[BM][17];   // 16 mnorm chains per word (+1 pad)
    __shared__ float sm_mn[BM];
    __shared__ int   widx[BM];
    __shared__ int   hist[NC];
    __shared__ int   is_last;

    const int t = threadIdx.x;
    const int wbase = blockIdx.x * BM;

    if (t < NC) hist[t] = 0;

    const int wo = t >> 4;   // 0..15: word group (8 words each)
    const int co = t & 15;   // 0..15: code group (8 codes each)
    const int lw = t >> 2;   // 0..63: loader row
    const int lq = t & 3;    // 0..3 : loader quad (== mnorm part index p)

    unsigned long long acc2[8][4];      // packed pairs: j = 2*jp (lo), 2*jp+1 (hi)
    #pragma unroll
    for (int i = 0; i < 8; i++)
        #pragma unroll
        for (int jp = 0; jp < 4; jp++) acc2[i][jp] = 0ull;

    float4 macc0 = make_float4(0.f, 0.f, 0.f, 0.f);   // mnorm chains, row p=0
    float4 macc1 = make_float4(0.f, 0.f, 0.f, 0.f);   // row p=1

    // register prefetch buffers (raw float4s; fadd done at store time)
    float4 pa00, pa01, pa10, pa11;      // A: [p][src]
    float4 pb0, pb1;                    // B: [p]

    // ---- prefetch chunk 0 ----
    {
        const size_t r0 = (size_t)(wbase + lw) * 2 * DIM + lq * 4;
        const size_t r1 = (size_t)(wbase + 64 + lw) * 2 * DIM + lq * 4;
        pa00 = *(const float4*)(emb + r0);
        pa01 = *(const float4*)(emb + r0 + DIM);
        pa10 = *(const float4*)(emb + r1);
        pa11 = *(const float4*)(emb + r1 + DIM);
        pb0  = *(const float4*)(cb + (size_t)lw * DIM + lq * 4);
        pb1  = *(const float4*)(cb + (size_t)(64 + lw) * DIM + lq * 4);
    }

    for (int c = 0; c < NCHUNK; c++) {
        __syncthreads();   // consumers done with smem from previous chunk

        // ---- store phase: A = fl(a+b) transposed, + mnorm accumulation ----
        {
            float s0 = __fadd_rn(pa00.x, pa01.x);
            float s1 = __fadd_rn(pa00.y, pa01.y);
            float s2 = __fadd_rn(pa00.z, pa01.z);
            float s3 = __fadd_rn(pa00.w, pa01.w);
            sm_m[lq * 4 + 0][lw] = s0;
            sm_m[lq * 4 + 1][lw] = s1;
            sm_m[lq * 4 + 2][lw] = s2;
            sm_m[lq * 4 + 3][lw] = s3;
            float m0 = __fmul_rn(s0, 0.5f), m1 = __fmul_rn(s1, 0.5f);
            float m2 = __fmul_rn(s2, 0.5f), m3 = __fmul_rn(s3, 0.5f);
            macc0.x = __fadd_rn(macc0.x, __fmul_rn(m0, m0));
            macc0.y = __fadd_rn(macc0.y, __fmul_rn(m1, m1));
            macc0.z = __fadd_rn(macc0.z, __fmul_rn(m2, m2));
            macc0.w = __fadd_rn(macc0.w, __fmul_rn(m3, m3));

            s0 = __fadd_rn(pa10.x, pa11.x);
            s1 = __fadd_rn(pa10.y, pa11.y);
            s2 = __fadd_rn(pa10.z, pa11.z);
            s3 = __fadd_rn(pa10.w, pa11.w);
            sm_m[lq * 4 + 0][64 + lw] = s0;
            sm_m[lq * 4 + 1][64 + lw] = s1;
            sm_m[lq * 4 + 2][64 + lw] = s2;
            sm_m[lq * 4 + 3][64 + lw] = s3;
            m0 = __fmul_rn(s0, 0.5f); m1 = __fmul_rn(s1, 0.5f);
            m2 = __fmul_rn(s2, 0.5f); m3 = __fmul_rn(s3, 0.5f);
            macc1.x = __fadd_rn(macc1.x, __fmul_rn(m0, m0));
            macc1.y = __fadd_rn(macc1.y, __fmul_rn(m1, m1));
            macc1.z = __fadd_rn(macc1.z, __fmul_rn(m2, m2));
            macc1.w = __fadd_rn(macc1.w, __fmul_rn(m3, m3));

            sm_c[lq * 4 + 0][lw] = pb0.x;
            sm_c[lq * 4 + 1][lw] = pb0.y;
            sm_c[lq * 4 + 2][lw] = pb0.z;
            sm_c[lq * 4 + 3][lw] = pb0.w;
            sm_c[lq * 4 + 0][64 + lw] = pb1.x;
            sm_c[lq * 4 + 1][64 + lw] = pb1.y;
            sm_c[lq * 4 + 2][64 + lw] = pb1.z;
            sm_c[lq * 4 + 3][64 + lw] = pb1.w;
        }
        __syncthreads();   // smem tiles ready

        // ---- prefetch next chunk (latency hidden under the FMAs below) ----
        if (c + 1 < NCHUNK) {
            const int kc = (c + 1) * BK;
            const size_t r0 = (size_t)(wbase + lw) * 2 * DIM + kc + lq * 4;
            const size_t r1 = (size_t)(wbase + 64 + lw) * 2 * DIM + kc + lq * 4;
            pa00 = *(const float4*)(emb + r0);
            pa01 = *(const float4*)(emb + r0 + DIM);
            pa10 = *(const float4*)(emb + r1);
            pa11 = *(const float4*)(emb + r1 + DIM);
            pb0  = *(const float4*)(cb + (size_t)lw * DIM + kc + lq * 4);
            pb1  = *(const float4*)(cb + (size_t)(64 + lw) * DIM + kc + lq * 4);
        }

        // ---- compute: 16 k-steps, packed f32x2 FMA (chains bit-identical) ----
        #pragma unroll
        for (int k = 0; k < BK; k++) {
            float4 a0 = *(const float4*)&sm_m[k][wo * 8];
            float4 a1 = *(const float4*)&sm_m[k][wo * 8 + 4];
            ulonglong2 q0 = *(const ulonglong2*)&sm_c[k][co * 8];
            ulonglong2 q1 = *(const ulonglong2*)&sm_c[k][co * 8 + 4];
            const unsigned long long bp0 = q0.x, bp1 = q0.y, bp2 = q1.x, bp3 = q1.y;
            const float av[8] = {a0.x, a0.y, a0.z, a0.w, a1.x, a1.y, a1.z, a1.w};
            #pragma unroll
            for (int i = 0; i < 8; i++) {
                const unsigned long long aa = dup2(av[i]);
                ffma2(acc2[i][0], aa, bp0);
                ffma2(acc2[i][1], aa, bp1);
                ffma2(acc2[i][2], aa, bp2);
                ffma2(acc2[i][3], aa, bp3);
            }
        }
    }

    // ---- mnorm fold (LLVM order), via smem ----
    sm_fold[lw][lq * 4 + 0] = macc0.x;
    sm_fold[lw][lq * 4 + 1] = macc0.y;
    sm_fold[lw][lq * 4 + 2] = macc0.z;
    sm_fold[lw][lq * 4 + 3] = macc0.w;
    sm_fold[64 + lw][lq * 4 + 0] = macc1.x;
    sm_fold[64 + lw][lq * 4 + 1] = macc1.y;
    sm_fold[64 + lw][lq * 4 + 2] = macc1.z;
    sm_fold[64 + lw][lq * 4 + 3] = macc1.w;
    __syncthreads();
    if (t < BM) {
        const float* s = sm_fold[t];
        float v0 = __fadd_rn(__fadd_rn(__fadd_rn(s[0], s[4]), s[8]),  s[12]);
        float v1 = __fadd_rn(__fadd_rn(__fadd_rn(s[1], s[5]), s[9]),  s[13]);
        float v2 = __fadd_rn(__fadd_rn(__fadd_rn(s[2], s[6]), s[10]), s[14]);
        float v3 = __fadd_rn(__fadd_rn(__fadd_rn(s[3], s[7]), s[11]), s[15]);
        sm_mn[t] = __fadd_rn(__fadd_rn(v0, v1), __fadd_rn(v2, v3));
    }
    __syncthreads();

    // ---- unpack accumulators ----
    float acc[8][8];
    #pragma unroll
    for (int i = 0; i < 8; i++)
        #pragma unroll
        for (int jp = 0; jp < 4; jp++) {
            float2 v = unpack2(acc2[i][jp]);
            acc[i][2 * jp]     = v.x;
            acc[i][2 * jp + 1] = v.y;
        }

    float cn[8];
    #pragma unroll
    for (int j = 0; j < 8; j++) cn[j] = __ldg(&g_cnorm[co * 8 + j]);
    float mn[8];
    #pragma unroll
    for (int i = 0; i < 8; i++) mn[i] = sm_mn[wo * 8 + i];

    // ---- argmin on d2 = fl(fl(mnorm - acc) + cnorm); first-min tie-break ----
    #pragma unroll
    for (int i = 0; i < 8; i++) {
        float best;
        int bidx = co * 8;
        {
            float tt = __fadd_rn(mn[i], -acc[i][0]);
            best = __fadd_rn(tt, cn[0]);
        }
        #pragma unroll
        for (int j = 1; j < 8; j++) {
            float tt = __fadd_rn(mn[i], -acc[i][j]);
            float d2 = __fadd_rn(tt, cn[j]);
            if (d2 < best) { best = d2; bidx = co * 8 + j; }
        }
        #pragma unroll
        for (int o = 8; o; o >>= 1) {
            float s2 = __shfl_down_sync(0xffffffffu, best, o, 16);
            int   i2 = __shfl_down_sync(0xffffffffu, bidx, o, 16);
            if (s2 < best || (s2 == best && i2 < bidx)) { best = s2; bidx = i2; }
        }
        if (co == 0) {
            const int w = wo * 8 + i;
            widx[w] = bidx;
            out_idx[wbase + w] = (float)bidx;
            atomicAdd(&hist[bidx], 1);
        }
    }
    __syncthreads();

    if (t < NC) {
        int h = hist[t];
        if (h) atomicAdd(&g_count[t], h);
    }

    // ---- gather-write word_embeddings (codebook L2-hot, coalesced stores) ----
    for (int f = t; f < BM * (DIM / 4); f += 256) {
        const int w  = f >> 7;
        const int c4 = f & 127;
        const int c  = widx[w];
        float4 v = *(const float4*)(cb + (size_t)c * DIM + c4 * 4);
        *(float4*)(out_emb + (size_t)(wbase + w) * DIM + c4 * 4) = v;
    }

    // ---- last-CTA loss: sum_c count[c]*s[c] / (NWORDS*DIM) ----
    __syncthreads();
    if (t == 0) {
        __threadfence();
        unsigned old = atomicAdd(&g_done, 1u);
        is_last = (old == gridDim.x - 1) ? 1 : 0;
    }
    __syncthreads();
    if (is_last && t < 32) {
        __threadfence();  // make all CTAs' g_count atomics visible
        float v = 0.f;
        #pragma unroll
        for (int q = 0; q < 4; q++) {
            const int c = q * 32 + t;
            const int cnt = *(volatile int*)&g_count[c];
            v = __fadd_rn(v, __fmul_rn((float)cnt, g_s_tab[c]));
        }
        #pragma unroll
        for (int o = 16; o; o >>= 1) v += __shfl_down_sync(0xffffffffu, v, o);
        if (t == 0) {
            out_loss[0] = v * (1.0f / ((float)NWORDS * (float)DIM));
            g_done = 0;  // reset for next graph replay
        }
    }
}

// ---------------------------------------------------------------------------
// Inputs (metadata order):
//   d_in[0] char_tokens int32 (unused)  d_in[1] char_embeddings f32 [16,4096,512]
//   d_in[2] word_codebook f32 [128,512] d_in[3] proj_w f32 [512,512]
//   d_in[4] proj_b f32 [512]
// Output (f32, flattened): [0,32768) indices | [.., +32768*512) embeddings | [last] loss
// ---------------------------------------------------------------------------
extern "C" void kernel_launch(void* const* d_in, const int* in_sizes, int n_in,
                              void* d_out, int out_size) {
    const float* emb = (const float*)d_in[1];
    const float* cb  = (const float*)d_in[2];
    const float* W   = (const float*)d_in[3];
    const float* b   = (const float*)d_in[4];
    float* out = (float*)d_out;

    float* out_idx  = out;
    float* out_emb  = out + NWORDS;
    float* out_loss = out + NWORDS + (size_t)NWORDS * DIM;

    prep_kernel<<<NC, 256>>>(cb, W, b);
    main_kernel<<<NWORDS / BM, 256>>>(emb, cb, out_idx, out_emb, out_loss);
}

// round 8
// speedup vs baseline: 1.7010x; 1.5641x over previous
#include <cuda_runtime.h>
#include <cstdint>

// Problem constants (fixed by the reference: B=16, L=4096, D=512, WORD_SIZE=128, WORD_LEN=2)
#define NWORDS 32768     // B * (L/2)
#define DIM    512
#define NC     128       // codebook rows
#define BM     128       // words per CTA tile
#define BK     16        // k-chunk
#define BMP    (BM + 4)  // padded smem leading dim
#define NCP    (NC + 4)
#define NCHUNK (DIM / BK)
#define PREP_CTAS 64
#define PREP_D    8      // d-columns per prep CTA

// Scratch (no allocations allowed -> __device__ globals)
__device__ float    g_s_part[PREP_CTAS][NC];  // partial ||P-C||^2 sums per d-chunk
__device__ int      g_count[NC];              // histogram of argmin indices
__device__ unsigned g_done;                   // last-CTA election (zero-init)

// ---- packed f32x2 helpers (each half = independent IEEE fp32 op) -----------
__device__ __forceinline__ unsigned long long dup2(float x) {
    unsigned long long r;
    asm("mov.b64 %0, {%1, %1};" : "=l"(r) : "f"(x));
    return r;
}
__device__ __forceinline__ void ffma2(unsigned long long& d,
                                      unsigned long long a,
                                      unsigned long long b) {
    asm("fma.rn.f32x2 %0, %1, %2, %0;" : "+l"(d) : "l"(a), "l"(b));
}
__device__ __forceinline__ float2 unpack2(unsigned long long v) {
    float2 f;
    asm("mov.b64 {%0, %1}, %2;" : "=f"(f.x), "=f"(f.y) : "l"(v));
    return f;
}

// ---------------------------------------------------------------------------
// Kernel 0 (prep v2): tiled GEMM P = C @ W^T + b ; per-CTA partial
//   g_s_part[bid][c] = sum_{d in chunk} (P[c,d] - C[c,d])^2
// Grid: 64 CTAs x 8 d-columns. FMA-bound (~2048 FMA/thread), W rows + C
// chunks staged in smem. Fixed fold order -> deterministic. CTA0 zeroes
// g_count. (Feeds ONLY the loss scalar; fp32 order noise irrelevant there.)
// ---------------------------------------------------------------------------
__global__ __launch_bounds__(256)
void prep_kernel(const float* __restrict__ cb,
                 const float* __restrict__ W,
                 const float* __restrict__ bias) {
    __shared__ float Wsm[PREP_D][DIM];     // 16 KB: 8 full W rows
    __shared__ float Csm[NC][36];          // 18.4 KB: 128 codes x 32-k chunk (pad->16B align)
    __shared__ float part[NC][9];          // per-(code, d) squared diffs

    const int t   = threadIdx.x;           // 256
    const int bid = blockIdx.x;
    const int dbase = bid * PREP_D;
    const int tx = t & 7;                  // d within chunk
    const int ty = t >> 3;                 // 0..31 -> codes ty*4..ty*4+3

    if (bid == 0 && t < NC) g_count[t] = 0;

    // load 8 W rows (rows dbase..dbase+7), coalesced float4
    {
        const float4* Wv = (const float4*)(W + (size_t)dbase * DIM);
        float4* Wd = (float4*)&Wsm[0][0];
        #pragma unroll
        for (int r = 0; r < 4; r++) Wd[t + r * 256] = Wv[t + r * 256];
    }

    float acc[4] = {0.f, 0.f, 0.f, 0.f};

    for (int kc = 0; kc < DIM; kc += 32) {
        __syncthreads();
        // stage C chunk [128][32]
        #pragma unroll
        for (int r = 0; r < 4; r++) {
            const int f4 = t + r * 256;          // 0..1023
            const int row = f4 >> 3, c4 = f4 & 7;
            float4 v = *(const float4*)(cb + (size_t)row * DIM + kc + c4 * 4);
            *(float4*)&Csm[row][c4 * 4] = v;
        }
        __syncthreads();
        #pragma unroll 8
        for (int k = 0; k < 32; k++) {
            const float wv = Wsm[tx][kc + k];
            #pragma unroll
            for (int i = 0; i < 4; i++)
                acc[i] = __fmaf_rn(Csm[ty * 4 + i][k], wv, acc[i]);
        }
    }

    const int d = dbase + tx;
    const float bv = bias[d];
    #pragma unroll
    for (int i = 0; i < 4; i++) {
        const int ci = ty * 4 + i;
        float diff = acc[i] + bv - cb[(size_t)ci * DIM + d];
        part[ci][tx] = diff * diff;
    }
    __syncthreads();
    if (t < NC) {
        const float* p = part[t];
        float s = p[0];
        #pragma unroll
        for (int i = 1; i < 8; i++) s = __fadd_rn(s, p[i]);  // fixed order
        g_s_part[bid][t] = s;
    }
}

// ---------------------------------------------------------------------------
// Kernel 1: fused  pair-sum -> mnorm(LLVM-order) + cnorm -> fp32 GEMM
//           (f32x2 packed, double-buffered smem, 1 barrier/chunk)
//           -> reference rounding chain -> argmin -> histogram -> gather
//           -> last-CTA loss.
//
// Bit-exactness invariants (verified rel_err==0.0 in R7, preserved):
//  * per-(word,code) dot: single fp32 accumulator, FMA over ascending k
//    (f32x2 halves are independent fp32 FMAs).
//  * mnorm: 16 chains part_p[l] = sum_i y[16i+4p+l] (i ascending via
//    ascending store-chunk order; loader thread lq == p, component == l),
//    fold ((P0+P1)+P2)+P3 then (v0+v1)+(v2+v3), y = fl(m^2),
//    m = fl(fl(a+b)*0.5).
//  * d2 = fl(fl(mnorm - acc) + cnorm), first-min tie-break.
//  * cnorm: per-CTA fixed-order chains (order noise ~1e-9 << 3e-5 grid).
// ---------------------------------------------------------------------------
__global__ __launch_bounds__(256, 2)
void main_kernel(const float* __restrict__ emb,   // [NWORDS*2, DIM]
                 const float* __restrict__ cb,    // [NC, DIM]
                 float* __restrict__ out_idx,     // NWORDS floats
                 float* __restrict__ out_emb,     // NWORDS*DIM floats
                 float* __restrict__ out_loss) {  // 1 float
    __shared__ float sm_m[2][BK][BMP];
    __shared__ float sm_c[2][BK][NCP];
    __shared__ float sm_fold[BM][17];   // 16 chains per word (+1 pad); reused for cnorm
    __shared__ float sm_mn[BM];
    __shared__ float sm_cn[NC];
    __shared__ float sm_ls[8];
    __shared__ int   widx[BM];
    __shared__ int   hist[NC];
    __shared__ int   is_last;

    const int t = threadIdx.x;
    const int wbase = blockIdx.x * BM;

    if (t < NC) hist[t] = 0;

    const int wo = t >> 4;   // 0..15: word group (8 words each)
    const int co = t & 15;   // 0..15: code group (8 codes each)
    const int lw = t >> 2;   // 0..63: loader row
    const int lq = t & 3;    // 0..3 : loader quad (== mnorm part index p)

    unsigned long long acc2[8][4];      // packed pairs: j = 2*jp (lo), 2*jp+1 (hi)
    #pragma unroll
    for (int i = 0; i < 8; i++)
        #pragma unroll
        for (int jp = 0; jp < 4; jp++) acc2[i][jp] = 0ull;

    float4 macc0 = make_float4(0.f, 0.f, 0.f, 0.f);   // mnorm chains, row p=lq, word lw
    float4 macc1 = make_float4(0.f, 0.f, 0.f, 0.f);   // word 64+lw
    float  cnacc0 = 0.f, cnacc1 = 0.f;                // cnorm partials (codes lw, 64+lw)

    float4 pa00, pa01, pa10, pa11, pb0, pb1;          // register prefetch

    auto do_ldg = [&](int c) {
        const int kc = c * BK;
        const size_t r0 = (size_t)(wbase + lw) * 2 * DIM + kc + lq * 4;
        const size_t r1 = r0 + (size_t)64 * 2 * DIM;
        pa00 = *(const float4*)(emb + r0);
        pa01 = *(const float4*)(emb + r0 + DIM);
        pa10 = *(const float4*)(emb + r1);
        pa11 = *(const float4*)(emb + r1 + DIM);
        pb0  = *(const float4*)(cb + (size_t)lw * DIM + kc + lq * 4);
        pb1  = *(const float4*)(cb + (size_t)(64 + lw) * DIM + kc + lq * 4);
    };

    auto do_store = [&](int buf) {
        float (*mm)[BMP] = sm_m[buf];
        float (*cc)[NCP] = sm_c[buf];
        float s0 = __fadd_rn(pa00.x, pa01.x);
        float s1 = __fadd_rn(pa00.y, pa01.y);
        float s2 = __fadd_rn(pa00.z, pa01.z);
        float s3 = __fadd_rn(pa00.w, pa01.w);
        mm[lq * 4 + 0][lw] = s0;
        mm[lq * 4 + 1][lw] = s1;
        mm[lq * 4 + 2][lw] = s2;
        mm[lq * 4 + 3][lw] = s3;
        float m0 = __fmul_rn(s0, 0.5f), m1 = __fmul_rn(s1, 0.5f);
        float m2 = __fmul_rn(s2, 0.5f), m3 = __fmul_rn(s3, 0.5f);
        macc0.x = __fadd_rn(macc0.x, __fmul_rn(m0, m0));
        macc0.y = __fadd_rn(macc0.y, __fmul_rn(m1, m1));
        macc0.z = __fadd_rn(macc0.z, __fmul_rn(m2, m2));
        macc0.w = __fadd_rn(macc0.w, __fmul_rn(m3, m3));

        s0 = __fadd_rn(pa10.x, pa11.x);
        s1 = __fadd_rn(pa10.y, pa11.y);
        s2 = __fadd_rn(pa10.z, pa11.z);
        s3 = __fadd_rn(pa10.w, pa11.w);
        mm[lq * 4 + 0][64 + lw] = s0;
        mm[lq * 4 + 1][64 + lw] = s1;
        mm[lq * 4 + 2][64 + lw] = s2;
        mm[lq * 4 + 3][64 + lw] = s3;
        m0 = __fmul_rn(s0, 0.5f); m1 = __fmul_rn(s1, 0.5f);
        m2 = __fmul_rn(s2, 0.5f); m3 = __fmul_rn(s3, 0.5f);
        macc1.x = __fadd_rn(macc1.x, __fmul_rn(m0, m0));
        macc1.y = __fadd_rn(macc1.y, __fmul_rn(m1, m1));
        macc1.z = __fadd_rn(macc1.z, __fmul_rn(m2, m2));
        macc1.w = __fadd_rn(macc1.w, __fmul_rn(m3, m3));

        cc[lq * 4 + 0][lw] = pb0.x;
        cc[lq * 4 + 1][lw] = pb0.y;
        cc[lq * 4 + 2][lw] = pb0.z;
        cc[lq * 4 + 3][lw] = pb0.w;
        cc[lq * 4 + 0][64 + lw] = pb1.x;
        cc[lq * 4 + 1][64 + lw] = pb1.y;
        cc[lq * 4 + 2][64 + lw] = pb1.z;
        cc[lq * 4 + 3][64 + lw] = pb1.w;
        cnacc0 = __fmaf_rn(pb0.x, pb0.x, cnacc0);
        cnacc0 = __fmaf_rn(pb0.y, pb0.y, cnacc0);
        cnacc0 = __fmaf_rn(pb0.z, pb0.z, cnacc0);
        cnacc0 = __fmaf_rn(pb0.w, pb0.w, cnacc0);
        cnacc1 = __fmaf_rn(pb1.x, pb1.x, cnacc1);
        cnacc1 = __fmaf_rn(pb1.y, pb1.y, cnacc1);
        cnacc1 = __fmaf_rn(pb1.z, pb1.z, cnacc1);
        cnacc1 = __fmaf_rn(pb1.w, pb1.w, cnacc1);
    };

    // ---- prologue: chunk 0 staged, chunk 1 in regs ----
    do_ldg(0);
    do_store(0);
    __syncthreads();
    do_ldg(1);

    // ---- pipelined main loop: ONE barrier per chunk ----
    for (int c = 0; c < NCHUNK; c++) {
        const float (*mm)[BMP] = sm_m[c & 1];
        const float (*cc)[NCP] = sm_c[c & 1];
        #pragma unroll
        for (int k = 0; k < BK; k++) {
            float4 a0 = *(const float4*)&mm[k][wo * 8];
            float4 a1 = *(const float4*)&mm[k][wo * 8 + 4];
            ulonglong2 q0 = *(const ulonglong2*)&cc[k][co * 8];
            ulonglong2 q1 = *(const ulonglong2*)&cc[k][co * 8 + 4];
            const unsigned long long bp0 = q0.x, bp1 = q0.y, bp2 = q1.x, bp3 = q1.y;
            const float av[8] = {a0.x, a0.y, a0.z, a0.w, a1.x, a1.y, a1.z, a1.w};
            #pragma unroll
            for (int i = 0; i < 8; i++) {
                const unsigned long long aa = dup2(av[i]);
                ffma2(acc2[i][0], aa, bp0);
                ffma2(acc2[i][1], aa, bp1);
                ffma2(acc2[i][2], aa, bp2);
                ffma2(acc2[i][3], aa, bp3);
            }
        }
        if (c + 1 < NCHUNK) {
            do_store((c + 1) & 1);              // ascending chunk order -> chains intact
            if (c + 2 < NCHUNK) do_ldg(c + 2);  // hide DRAM latency under next compute
            __syncthreads();
        }
    }

    // ---- mnorm fold (LLVM order) ----
    sm_fold[lw][lq * 4 + 0] = macc0.x;
    sm_fold[lw][lq * 4 + 1] = macc0.y;
    sm_fold[lw][lq * 4 + 2] = macc0.z;
    sm_fold[lw][lq * 4 + 3] = macc0.w;
    sm_fold[64 + lw][lq * 4 + 0] = macc1.x;
    sm_fold[64 + lw][lq * 4 + 1] = macc1.y;
    sm_fold[64 + lw][lq * 4 + 2] = macc1.z;
    sm_fold[64 + lw][lq * 4 + 3] = macc1.w;
    __syncthreads();
    if (t < BM) {
        const float* s = sm_fold[t];
        float v0 = __fadd_rn(__fadd_rn(__fadd_rn(s[0], s[4]), s[8]),  s[12]);
        float v1 = __fadd_rn(__fadd_rn(__fadd_rn(s[1], s[5]), s[9]),  s[13]);
        float v2 = __fadd_rn(__fadd_rn(__fadd_rn(s[2], s[6]), s[10]), s[14]);
        float v3 = __fadd_rn(__fadd_rn(__fadd_rn(s[3], s[7]), s[11]), s[15]);
        sm_mn[t] = __fadd_rn(__fadd_rn(v0, v1), __fadd_rn(v2, v3));
    }
    __syncthreads();

    // ---- cnorm fold (fixed order; reuses sm_fold) ----
    sm_fold[lw][lq]      = cnacc0;
    sm_fold[64 + lw][lq] = cnacc1;
    __syncthreads();
    if (t < NC) {
        const float* s = sm_fold[t];
        sm_cn[t] = __fadd_rn(__fadd_rn(__fadd_rn(s[0], s[1]), s[2]), s[3]);
    }
    __syncthreads();

    // ---- unpack accumulators ----
    float acc[8][8];
    #pragma unroll
    for (int i = 0; i < 8; i++)
        #pragma unroll
        for (int jp = 0; jp < 4; jp++) {
            float2 v = unpack2(acc2[i][jp]);
            acc[i][2 * jp]     = v.x;
            acc[i][2 * jp + 1] = v.y;
        }

    float cn[8];
    #pragma unroll
    for (int j = 0; j < 8; j++) cn[j] = sm_cn[co * 8 + j];
    float mn[8];
    #pragma unroll
    for (int i = 0; i < 8; i++) mn[i] = sm_mn[wo * 8 + i];

    // ---- argmin on d2 = fl(fl(mnorm - acc) + cnorm); first-min tie-break ----
    #pragma unroll
    for (int i = 0; i < 8; i++) {
        float best;
        int bidx = co * 8;
        {
            float tt = __fadd_rn(mn[i], -acc[i][0]);
            best = __fadd_rn(tt, cn[0]);
        }
        #pragma unroll
        for (int j = 1; j < 8; j++) {
            float tt = __fadd_rn(mn[i], -acc[i][j]);
            float d2 = __fadd_rn(tt, cn[j]);
            if (d2 < best) { best = d2; bidx = co * 8 + j; }
        }
        #pragma unroll
        for (int o = 8; o; o >>= 1) {
            float s2 = __shfl_down_sync(0xffffffffu, best, o, 16);
            int   i2 = __shfl_down_sync(0xffffffffu, bidx, o, 16);
            if (s2 < best || (s2 == best && i2 < bidx)) { best = s2; bidx = i2; }
        }
        if (co == 0) {
            const int w = wo * 8 + i;
            widx[w] = bidx;
            out_idx[wbase + w] = (float)bidx;
            atomicAdd(&hist[bidx], 1);
        }
    }
    __syncthreads();

    if (t < NC) {
        int h = hist[t];
        if (h) atomicAdd(&g_count[t], h);
    }

    // ---- gather-write word_embeddings (codebook L2-hot, coalesced stores) ----
    for (int f = t; f < BM * (DIM / 4); f += 256) {
        const int w  = f >> 7;
        const int c4 = f & 127;
        const int c  = widx[w];
        float4 v = *(const float4*)(cb + (size_t)c * DIM + c4 * 4);
        *(float4*)(out_emb + (size_t)(wbase + w) * DIM + c4 * 4) = v;
    }

    // ---- last-CTA loss: sum_c count[c] * (sum_p s_part[p][c]) / (NWORDS*DIM) ----
    __syncthreads();
    if (t == 0) {
        __threadfence();
        unsigned old = atomicAdd(&g_done, 1u);
        is_last = (old == gridDim.x - 1) ? 1 : 0;
    }
    __syncthreads();
    if (is_last) {
        float v = 0.f;
        if (t < NC) {
            __threadfence();  // make all CTAs' g_count atomics visible
            float s = 0.f;
            #pragma unroll 8
            for (int p = 0; p < PREP_CTAS; p++)
                s = __fadd_rn(s, g_s_part[p][t]);       // fixed order
            const int cnt = *(volatile int*)&g_count[t];
            v = __fmul_rn((float)cnt, s);
        }
        #pragma unroll
        for (int o = 16; o; o >>= 1) v += __shfl_down_sync(0xffffffffu, v, o);
        if ((t & 31) == 0) sm_ls[t >> 5] = v;
        __syncthreads();
        if (t == 0) {
            float s = sm_ls[0];
            #pragma unroll
            for (int i = 1; i < 8; i++) s = __fadd_rn(s, sm_ls[i]);
            out_loss[0] = s * (1.0f / ((float)NWORDS * (float)DIM));
            g_done = 0;  // reset for next graph replay
        }
    }
}

// ---------------------------------------------------------------------------
// Inputs (metadata order):
//   d_in[0] char_tokens int32 (unused)  d_in[1] char_embeddings f32 [16,4096,512]
//   d_in[2] word_codebook f32 [128,512] d_in[3] proj_w f32 [512,512]
//   d_in[4] proj_b f32 [512]
// Output (f32, flattened): [0,32768) indices | [.., +32768*512) embeddings | [last] loss
// ---------------------------------------------------------------------------
extern "C" void kernel_launch(void* const* d_in, const int* in_sizes, int n_in,
                              void* d_out, int out_size) {
    const float* emb = (const float*)d_in[1];
    const float* cb  = (const float*)d_in[2];
    const float* W   = (const float*)d_in[3];
    const float* b   = (const float*)d_in[4];
    float* out = (float*)d_out;

    float* out_idx  = out;
    float* out_emb  = out + NWORDS;
    float* out_loss = out + NWORDS + (size_t)NWORDS * DIM;

    prep_kernel<<<PREP_CTAS, 256>>>(cb, W, b);
    main_kernel<<<NWORDS / BM, 256>>>(emb, cb, out_idx, out_emb, out_loss);
}